// round 17
// baseline (speedup 1.0000x reference)
#include <cuda_runtime.h>
#include <cuda_bf16.h>
#include <cstdint>

// PoseDisentangler: bone_len + bone_dir from H36M skeleton.
// pose_3d: (B=128, N=4096, J=17, 3) fp32, row of 51 floats per (b,n).
// out: [bone_len (B*N*16)] ++ [bone_dir (B*N*48)]
//
// R15: intra-CTA TMA pipeline. Each CTA processes TILES=4 tiles of 64 rows:
// double-buffered bulk loads (tile t+2 issued while computing t), single
// result buffer recycled via bulk wait_group 0 (stores drain a tile ahead).
// LSU only does compute LDS + result STS (the R13 win, preserved).

#define ROWS 64
#define THREADS 256
#define TILES 4
#define ROW_FLOATS 51
#define NB 16
#define IN_FLOATS  (ROWS * ROW_FLOATS)      // 3264
#define IN_BYTES   (IN_FLOATS * 4)          // 13056
#define LEN_BYTES  (ROWS * NB * 4)          // 4096
#define DIR_BYTES  (ROWS * NB * 3 * 4)      // 12288

// PARENT[j] packed 4 bits per bone: {0,1,2,0,4,5,0,7,8,9,8,11,12,8,14,15}
#define PARENT_PACK 0xFE8CB89870540210ULL
__device__ __forceinline__ int parent_of(int j) {
    return (int)((PARENT_PACK >> (j * 4)) & 15ULL);
}

__device__ __forceinline__ uint32_t smem_u32(const void* p) {
    uint32_t a;
    asm("{ .reg .u64 t; cvta.to.shared.u64 t, %1; cvt.u32.u64 %0, t; }"
        : "=r"(a) : "l"(p));
    return a;
}

__device__ __forceinline__ void mbar_wait(uint32_t mb, uint32_t parity) {
    uint32_t done;
    asm volatile(
        "{\n\t.reg .pred p;\n\t"
        "mbarrier.try_wait.parity.acquire.cta.shared::cta.b64 p, [%1], %2;\n\t"
        "selp.b32 %0, 1, 0, p;\n\t}"
        : "=r"(done) : "r"(mb), "r"(parity) : "memory");
    if (!done) {
        asm volatile(
            "{\n\t.reg .pred P1;\n\t"
            "WL_%=:\n\t"
            "mbarrier.try_wait.parity.acquire.cta.shared::cta.b64 P1, [%0], %1, 0x989680;\n\t"
            "@P1 bra.uni WD_%=;\n\t"
            "bra.uni WL_%=;\n\t"
            "WD_%=:\n\t}"
            :: "r"(mb), "r"(parity) : "memory");
    }
}

__device__ __forceinline__ void tma_load(uint32_t dst, const char* src, uint32_t mb) {
    asm volatile("mbarrier.arrive.expect_tx.shared.b64 _, [%0], %1;"
                 :: "r"(mb), "r"((uint32_t)IN_BYTES) : "memory");
    asm volatile("cp.async.bulk.shared::cta.global.mbarrier::complete_tx::bytes "
                 "[%0], [%1], %2, [%3];"
                 :: "r"(dst), "l"(src), "r"((uint32_t)IN_BYTES), "r"(mb)
                 : "memory");
}

__global__ __launch_bounds__(THREADS, 5)
void pose_bones_kernel(const float* __restrict__ in,
                       float* __restrict__ len_out,
                       float* __restrict__ dir_out)
{
    __shared__ alignas(16) float s_in[2][IN_FLOATS];        // 26112 B
    __shared__ alignas(16) float s_len[ROWS * NB];          //  4096 B
    __shared__ alignas(16) float s_dir[ROWS * NB * 3];      // 12288 B
    __shared__ alignas(8)  unsigned long long mbar[2];

    const int tid = threadIdx.x;
    const uint32_t mb0 = smem_u32(&mbar[0]);
    const uint32_t mb1 = smem_u32(&mbar[1]);
    const uint32_t sin0 = smem_u32(&s_in[0][0]);
    const uint32_t sin1 = smem_u32(&s_in[1][0]);

    const size_t tile0 = (size_t)blockIdx.x * TILES;
    const char* gin = reinterpret_cast<const char*>(in) + tile0 * IN_BYTES;

    if (tid == 0) {
        asm volatile("mbarrier.init.shared.b64 [%0], 1;" :: "r"(mb0) : "memory");
        asm volatile("mbarrier.init.shared.b64 [%0], 1;" :: "r"(mb1) : "memory");
    }
    __syncthreads();

    // Prefetch tiles 0 and 1.
    if (tid == 0) {
        tma_load(sin0, gin + 0 * IN_BYTES, mb0);
        tma_load(sin1, gin + 1 * IN_BYTES, mb1);
    }

    const int row = tid >> 2;
    const int q   = tid & 3;

    #pragma unroll
    for (int t = 0; t < TILES; ++t) {
        const int buf = t & 1;
        const uint32_t ph = (t >> 1) & 1;

        mbar_wait(buf ? mb1 : mb0, ph);

        // Compute tile t -> registers.
        const float* __restrict__ p = s_in[buf] + row * ROW_FLOATS;
        float l[4];
        float d[12];
        #pragma unroll
        for (int jj = 0; jj < 4; ++jj) {
            const int j  = q * 4 + jj;
            const int ch = (j + 1) * 3;
            const int pa = parent_of(j) * 3;
            float vx = p[ch + 0] - p[pa + 0];
            float vy = p[ch + 1] - p[pa + 1];
            float vz = p[ch + 2] - p[pa + 2];
            float ss  = fmaxf(vx * vx + vy * vy + vz * vz, 1e-30f);
            float inv = rsqrtf(ss);
            l[jj]         = ss * inv;              // == sqrt(ss)
            d[jj * 3 + 0] = vx * inv;
            d[jj * 3 + 1] = vy * inv;
            d[jj * 3 + 2] = vz * inv;
        }

        // Result buffer free? (previous tile's bulk store must have retired)
        if (tid == 0) {
            asm volatile("cp.async.bulk.wait_group 0;" ::: "memory");
        }
        __syncthreads();

        // Stage results, unpadded exact output layout (conflict-free f4 STS).
        *reinterpret_cast<float4*>(s_len + row * NB + q * 4) =
            make_float4(l[0], l[1], l[2], l[3]);
        float4* sd = reinterpret_cast<float4*>(s_dir + row * (NB * 3) + q * 12);
        sd[0] = make_float4(d[0], d[1], d[2],  d[3]);
        sd[1] = make_float4(d[4], d[5], d[6],  d[7]);
        sd[2] = make_float4(d[8], d[9], d[10], d[11]);
        __syncthreads();

        if (tid == 0) {
            asm volatile("fence.proxy.async.shared::cta;" ::: "memory");
            char* dl = reinterpret_cast<char*>(len_out) + (tile0 + t) * LEN_BYTES;
            char* dd = reinterpret_cast<char*>(dir_out) + (tile0 + t) * DIR_BYTES;
            asm volatile("cp.async.bulk.global.shared::cta.bulk_group [%0], [%1], %2;"
                         :: "l"(dl), "r"(smem_u32(s_len)), "r"((uint32_t)LEN_BYTES) : "memory");
            asm volatile("cp.async.bulk.global.shared::cta.bulk_group [%0], [%1], %2;"
                         :: "l"(dd), "r"(smem_u32(s_dir)), "r"((uint32_t)DIR_BYTES) : "memory");
            asm volatile("cp.async.bulk.commit_group;" ::: "memory");
            // Prefetch tile t+2 into the buffer we just finished reading.
            if (t + 2 < TILES)
                tma_load(buf ? sin1 : sin0, gin + (size_t)(t + 2) * IN_BYTES,
                         buf ? mb1 : mb0);
        }
    }

    // Drain outstanding stores before CTA exit.
    if (tid == 0) {
        asm volatile("cp.async.bulk.wait_group 0;" ::: "memory");
    }
}

extern "C" void kernel_launch(void* const* d_in, const int* in_sizes, int n_in,
                              void* d_out, int out_size)
{
    const float* in = (const float*)d_in[0];
    const int rows = in_sizes[0] / ROW_FLOATS;         // B*N = 524288

    float* len_out = (float*)d_out;
    float* dir_out = len_out + (size_t)rows * NB;

    const int blocks = rows / (ROWS * TILES);          // exact: 2048
    pose_bones_kernel<<<blocks, THREADS>>>(in, len_out, dir_out);
}